// round 5
// baseline (speedup 1.0000x reference)
#include <cuda_runtime.h>
#include <cstdint>
#include <cstddef>

// Problem constants
#define B_SZ  4
#define S_LEN 2048
#define E_DIM 1024
#define NH    16
#define HD    64
#define M_TOT (B_SZ * S_LEN)   // 8192
#define N_TOT (3 * E_DIM)      // 3072
#define K_TOT E_DIM            // 1024

// Scratch: Q/K/V in [B,H,S,D] layout (device globals — no runtime alloc allowed)
__device__ float g_q[(size_t)B_SZ * NH * S_LEN * HD];
__device__ float g_k[(size_t)B_SZ * NH * S_LEN * HD];
__device__ float g_v[(size_t)B_SZ * NH * S_LEN * HD];

// ---- packed f32x2 helpers (Blackwell sm_103a) ----
__device__ __forceinline__ unsigned long long dup2(float x) {
    unsigned long long r;
    unsigned u = __float_as_uint(x);
    asm("mov.b64 %0, {%1, %1};" : "=l"(r) : "r"(u));
    return r;
}
__device__ __forceinline__ void fma2(unsigned long long& acc,
                                     unsigned long long a, unsigned long long b) {
    asm("fma.rn.f32x2 %0, %1, %2, %0;" : "+l"(acc) : "l"(a), "l"(b));
}
__device__ __forceinline__ void mul2(unsigned long long& acc, unsigned long long a) {
    asm("mul.rn.f32x2 %0, %0, %1;" : "+l"(acc) : "l"(a));
}
__device__ __forceinline__ float2 unpk(unsigned long long v) {
    unsigned lo, hi;
    asm("mov.b64 {%0, %1}, %2;" : "=r"(lo), "=r"(hi) : "l"(v));
    return make_float2(__uint_as_float(lo), __uint_as_float(hi));
}

// ============================================================================
// Kernel 1: fused QKV GEMM.  qkv[m,n] = x[m,:] @ W[:,n]
// 128x128 tile, BK=16, 256 threads, 8x8 microtile as f32x2 pairs along N.
// Epilogue scatters into g_q/g_k/g_v in [B,H,S,D] layout; Q scaled by 0.125.
// ============================================================================
__global__ __launch_bounds__(256, 2) void qkv_gemm(const float* __restrict__ x,
                                                   const float* __restrict__ w) {
    __shared__ float As[16][128];   // A transposed: As[k][m]
    __shared__ float Bs[16][128];   // B natural:    Bs[k][n]

    const int tid = threadIdx.x;
    const int tx = tid & 15, ty = tid >> 4;
    const int m0 = blockIdx.y << 7, n0 = blockIdx.x << 7;

    unsigned long long acc[8][4];
#pragma unroll
    for (int i = 0; i < 8; i++)
#pragma unroll
        for (int j = 0; j < 4; j++) acc[i][j] = 0ULL;

    const int mA = tid >> 2;          // 0..63
    const int kA = (tid & 3) << 2;    // 0,4,8,12
    const int kB = tid >> 5;          // 0..7
    const int nB = (tid & 31) << 2;   // 0..124

    const float* ap = x + (size_t)(m0 + mA) * K_TOT + kA;
    const float* bp = w + (size_t)kB * N_TOT + n0 + nB;

    for (int k0 = 0; k0 < K_TOT; k0 += 16) {
        // load A tile (transposed store)
        float4 a0 = *(const float4*)(ap + k0);
        float4 a1 = *(const float4*)(ap + (size_t)64 * K_TOT + k0);
        As[kA + 0][mA] = a0.x; As[kA + 1][mA] = a0.y;
        As[kA + 2][mA] = a0.z; As[kA + 3][mA] = a0.w;
        As[kA + 0][mA + 64] = a1.x; As[kA + 1][mA + 64] = a1.y;
        As[kA + 2][mA + 64] = a1.z; As[kA + 3][mA + 64] = a1.w;
        // load B tile (natural)
        *(float4*)&Bs[kB][nB]     = *(const float4*)(bp + (size_t)k0 * N_TOT);
        *(float4*)&Bs[kB + 8][nB] = *(const float4*)(bp + (size_t)(k0 + 8) * N_TOT);
        __syncthreads();

#pragma unroll
        for (int k = 0; k < 16; k++) {
            float a[8];
            *(float4*)&a[0] = *(float4*)&As[k][ty << 2];
            *(float4*)&a[4] = *(float4*)&As[k][64 + (ty << 2)];
            unsigned long long b[4];
            {
                ulonglong2 t0 = *(ulonglong2*)&Bs[k][tx << 2];
                ulonglong2 t1 = *(ulonglong2*)&Bs[k][64 + (tx << 2)];
                b[0] = t0.x; b[1] = t0.y; b[2] = t1.x; b[3] = t1.y;
            }
#pragma unroll
            for (int i = 0; i < 8; i++) {
                unsigned long long a2 = dup2(a[i]);
                fma2(acc[i][0], a2, b[0]);
                fma2(acc[i][1], a2, b[1]);
                fma2(acc[i][2], a2, b[2]);
                fma2(acc[i][3], a2, b[3]);
            }
        }
        __syncthreads();
    }

    // epilogue: scatter into [B,H,S,D]-layout Q/K/V
#pragma unroll
    for (int i = 0; i < 8; i++) {
        const int m = m0 + ((i < 4) ? ((ty << 2) + i) : (64 + (ty << 2) + i - 4));
        const int bb = m >> 11;             // /S_LEN
        const int s  = m & (S_LEN - 1);
#pragma unroll
        for (int j = 0; j < 4; j++) {
            float2 v = unpk(acc[i][j]);
            const int nbase = n0 + ((j < 2) ? ((tx << 2) + (j << 1))
                                            : (64 + (tx << 2) + ((j - 2) << 1)));
#pragma unroll
            for (int u = 0; u < 2; u++) {
                const int n = nbase + u;
                const float val = (u == 0) ? v.x : v.y;
                const int which = n >> 10;      // 0=q,1=k,2=v
                const int rem = n & 1023;
                const int h = rem >> 6;
                const int d = rem & 63;
                const size_t dst = (((size_t)(bb * NH + h)) * S_LEN + s) * HD + d;
                if (which == 0)      g_q[dst] = val * 0.125f;   // fold 1/sqrt(D)
                else if (which == 1) g_k[dst] = val;
                else                 g_v[dst] = val;
            }
        }
    }
}

// ============================================================================
// Kernel 2: causal flash attention, fp32, f32x2 packed FMA.
// One CTA = 64 Q rows of one (b,h).  K tile stored transposed [d][c] with a
// 16B-chunk XOR swizzle; the same buffer is reused for P after the S-gemm.
// ============================================================================
__global__ __launch_bounds__(256, 2) void attn_kernel(float* __restrict__ out) {
    __shared__ float Qs[64 * 64];    // [r][d]
    __shared__ float KPs[64 * 64];   // K^T swizzled [d][c], then P [r][c]
    __shared__ float Vs[64 * 64];    // [c][d]

    const int tid = threadIdx.x;
    const int tx = tid & 15, ty = tid >> 4;
    const int qtile = (int)gridDim.x - 1 - (int)blockIdx.x;  // long blocks first
    const int bh = blockIdx.y;
    const int qbase = qtile << 6;
    const float NEG_INF = __int_as_float(0xff800000);

    const float* Qg = g_q + (size_t)bh * S_LEN * HD;
    const float* Kg = g_k + (size_t)bh * S_LEN * HD;
    const float* Vg = g_v + (size_t)bh * S_LEN * HD;

    const int lr = tid >> 2;   // 0..63 (row)
    const int lv = tid & 3;    // 0..3  (vec)

    // load Q tile (already scaled by 1/sqrt(D))
#pragma unroll
    for (int c = 0; c < 4; c++) {
        const int dv = lv + (c << 2);
        *(float4*)&Qs[lr * 64 + (dv << 2)] =
            *(const float4*)(Qg + (size_t)(qbase + lr) * HD + (dv << 2));
    }

    float mrow[4], lrow[4];
    unsigned long long oacc[4][2];
#pragma unroll
    for (int i = 0; i < 4; i++) {
        mrow[i] = NEG_INF; lrow[i] = 0.0f;
        oacc[i][0] = 0ULL; oacc[i][1] = 0ULL;
    }

    for (int kt = 0; kt <= qtile; kt++) {
        const int kbase = kt << 6;
        __syncthreads();  // prior-iter reads done (and Q stores before 1st gemm)

        // load K (transposed + swizzled) and V (natural)
#pragma unroll
        for (int c = 0; c < 4; c++) {
            const int dv = lv + (c << 2);
            const int d0 = dv << 2;
            float4 kv = *(const float4*)(Kg + (size_t)(kbase + lr) * HD + d0);
            const int q = lr >> 2, lo = lr & 3;
            KPs[(d0 + 0) * 64 + ((q ^ ((d0 + 0) & 15)) << 2) + lo] = kv.x;
            KPs[(d0 + 1) * 64 + ((q ^ ((d0 + 1) & 15)) << 2) + lo] = kv.y;
            KPs[(d0 + 2) * 64 + ((q ^ ((d0 + 2) & 15)) << 2) + lo] = kv.z;
            KPs[(d0 + 3) * 64 + ((q ^ ((d0 + 3) & 15)) << 2) + lo] = kv.w;
            *(float4*)&Vs[lr * 64 + d0] =
                *(const float4*)(Vg + (size_t)(kbase + lr) * HD + d0);
        }
        __syncthreads();

        // S = Q K^T : rows r = 4ty+i, cols c = 4tx+j (pairs packed)
        unsigned long long sc2[4][2];
#pragma unroll
        for (int i = 0; i < 4; i++) { sc2[i][0] = 0ULL; sc2[i][1] = 0ULL; }

#pragma unroll
        for (int d0 = 0; d0 < 64; d0 += 4) {
            float4 af[4];
#pragma unroll
            for (int i = 0; i < 4; i++)
                af[i] = *(float4*)&Qs[((ty << 2) + i) * 64 + d0];
            unsigned long long bf[4][2];
#pragma unroll
            for (int dd = 0; dd < 4; dd++) {
                const int d = d0 + dd;
                ulonglong2 t = *(ulonglong2*)&KPs[d * 64 + ((tx ^ (d & 15)) << 2)];
                bf[dd][0] = t.x; bf[dd][1] = t.y;
            }
#pragma unroll
            for (int i = 0; i < 4; i++) {
                unsigned long long a0 = dup2(af[i].x), a1 = dup2(af[i].y);
                unsigned long long a2 = dup2(af[i].z), a3 = dup2(af[i].w);
                fma2(sc2[i][0], a0, bf[0][0]); fma2(sc2[i][1], a0, bf[0][1]);
                fma2(sc2[i][0], a1, bf[1][0]); fma2(sc2[i][1], a1, bf[1][1]);
                fma2(sc2[i][0], a2, bf[2][0]); fma2(sc2[i][1], a2, bf[2][1]);
                fma2(sc2[i][0], a3, bf[3][0]); fma2(sc2[i][1], a3, bf[3][1]);
            }
        }

        // online softmax (row-wise, 16-lane shfl reductions)
        const bool diag = (kt == qtile);
        float pfrag[4][4];
#pragma unroll
        for (int i = 0; i < 4; i++) {
            float2 p01 = unpk(sc2[i][0]);
            float2 p23 = unpk(sc2[i][1]);
            float s0 = p01.x, s1 = p01.y, s2 = p23.x, s3 = p23.y;
            if (diag) {
                const int rg = qbase + (ty << 2) + i;
                const int cg = kbase + (tx << 2);
                if (cg + 0 > rg) s0 = NEG_INF;
                if (cg + 1 > rg) s1 = NEG_INF;
                if (cg + 2 > rg) s2 = NEG_INF;
                if (cg + 3 > rg) s3 = NEG_INF;
            }
            float rmax = fmaxf(fmaxf(s0, s1), fmaxf(s2, s3));
#pragma unroll
            for (int o = 8; o >= 1; o >>= 1)
                rmax = fmaxf(rmax, __shfl_xor_sync(0xffffffffu, rmax, o, 16));
            const float mnew = fmaxf(mrow[i], rmax);
            const float alpha = __expf(mrow[i] - mnew);
            const float p0 = __expf(s0 - mnew);
            const float p1 = __expf(s1 - mnew);
            const float p2 = __expf(s2 - mnew);
            const float p3 = __expf(s3 - mnew);
            float rsum = (p0 + p1) + (p2 + p3);
#pragma unroll
            for (int o = 8; o >= 1; o >>= 1)
                rsum += __shfl_xor_sync(0xffffffffu, rsum, o, 16);
            lrow[i] = lrow[i] * alpha + rsum;
            mrow[i] = mnew;
            unsigned long long al2 = dup2(alpha);
            mul2(oacc[i][0], al2);
            mul2(oacc[i][1], al2);
            pfrag[i][0] = p0; pfrag[i][1] = p1; pfrag[i][2] = p2; pfrag[i][3] = p3;
        }

        __syncthreads();  // everyone done reading KPs as K
#pragma unroll
        for (int i = 0; i < 4; i++)
            *(float4*)&KPs[((ty << 2) + i) * 64 + (tx << 2)] = *(float4*)&pfrag[i][0];
        __syncthreads();  // P visible

        // O += P @ V : rows r = 4ty+i, d-cols 4tx+jj (pairs packed)
#pragma unroll
        for (int c0 = 0; c0 < 64; c0 += 4) {
            float4 pf[4];
#pragma unroll
            for (int i = 0; i < 4; i++)
                pf[i] = *(float4*)&KPs[((ty << 2) + i) * 64 + c0];
            unsigned long long vf[4][2];
#pragma unroll
            for (int k = 0; k < 4; k++) {
                ulonglong2 t = *(ulonglong2*)&Vs[(c0 + k) * 64 + (tx << 2)];
                vf[k][0] = t.x; vf[k][1] = t.y;
            }
#pragma unroll
            for (int i = 0; i < 4; i++) {
                unsigned long long p0 = dup2(pf[i].x), p1 = dup2(pf[i].y);
                unsigned long long p2 = dup2(pf[i].z), p3 = dup2(pf[i].w);
                fma2(oacc[i][0], p0, vf[0][0]); fma2(oacc[i][1], p0, vf[0][1]);
                fma2(oacc[i][0], p1, vf[1][0]); fma2(oacc[i][1], p1, vf[1][1]);
                fma2(oacc[i][0], p2, vf[2][0]); fma2(oacc[i][1], p2, vf[2][1]);
                fma2(oacc[i][0], p3, vf[3][0]); fma2(oacc[i][1], p3, vf[3][1]);
            }
        }
    }

    // write output: out[b, s, h*64 + d]
    const int b = bh >> 4, h = bh & 15;
#pragma unroll
    for (int i = 0; i < 4; i++) {
        const int s = qbase + (ty << 2) + i;
        const float inv = 1.0f / lrow[i];
        float2 o01 = unpk(oacc[i][0]);
        float2 o23 = unpk(oacc[i][1]);
        float4 o4 = make_float4(o01.x * inv, o01.y * inv, o23.x * inv, o23.y * inv);
        *(float4*)(out + ((size_t)b * S_LEN + s) * E_DIM + h * HD + (tx << 2)) = o4;
    }
}

// ============================================================================
// Launch
// ============================================================================
extern "C" void kernel_launch(void* const* d_in, const int* in_sizes, int n_in,
                              void* d_out, int out_size) {
    (void)in_sizes; (void)n_in; (void)out_size;
    const float* x = (const float*)d_in[0];   // [4,2048,1024] fp32
    const float* w = (const float*)d_in[1];   // [1024,3072] fp32
    float* out = (float*)d_out;               // [4,2048,1024] fp32

    qkv_gemm<<<dim3(N_TOT / 128, M_TOT / 128), 256>>>(x, w);
    attn_kernel<<<dim3(S_LEN / 64, B_SZ * NH), 256>>>(out);
}

// round 6
// speedup vs baseline: 1.0604x; 1.0604x over previous
#include <cuda_runtime.h>
#include <cstdint>
#include <cstddef>

// Problem constants
#define B_SZ  4
#define S_LEN 2048
#define E_DIM 1024
#define NH    16
#define HD    64
#define M_TOT (B_SZ * S_LEN)   // 8192
#define N_TOT (3 * E_DIM)      // 3072
#define K_TOT E_DIM            // 1024

// Scratch: Q/K/V in [B,H,S,D] layout (device globals — no runtime alloc allowed)
__device__ float g_q[(size_t)B_SZ * NH * S_LEN * HD];
__device__ float g_k[(size_t)B_SZ * NH * S_LEN * HD];
__device__ float g_v[(size_t)B_SZ * NH * S_LEN * HD];

// ---- packed f32x2 helpers (Blackwell sm_103a) ----
__device__ __forceinline__ unsigned long long dup2(float x) {
    unsigned long long r;
    unsigned u = __float_as_uint(x);
    asm("mov.b64 %0, {%1, %1};" : "=l"(r) : "r"(u));
    return r;
}
__device__ __forceinline__ void fma2(unsigned long long& acc,
                                     unsigned long long a, unsigned long long b) {
    asm("fma.rn.f32x2 %0, %1, %2, %0;" : "+l"(acc) : "l"(a), "l"(b));
}
__device__ __forceinline__ void mul2(unsigned long long& acc, unsigned long long a) {
    asm("mul.rn.f32x2 %0, %0, %1;" : "+l"(acc) : "l"(a));
}
__device__ __forceinline__ float2 unpk(unsigned long long v) {
    unsigned lo, hi;
    asm("mov.b64 {%0, %1}, %2;" : "=r"(lo), "=r"(hi) : "l"(v));
    return make_float2(__uint_as_float(lo), __uint_as_float(hi));
}

// ============================================================================
// Kernel 1: fused QKV GEMM.  qkv[m,n] = x[m,:] @ W[:,n]
// 128x128 tile, BK=16, 256 threads, 8x8 microtile as f32x2 pairs along N.
// Epilogue scatters into g_q/g_k/g_v in [B,H,S,D] layout; Q scaled by 0.125.
// ============================================================================
__global__ __launch_bounds__(256, 2) void qkv_gemm(const float* __restrict__ x,
                                                   const float* __restrict__ w) {
    __shared__ float As[16][128];   // A transposed: As[k][m]
    __shared__ float Bs[16][128];   // B natural:    Bs[k][n]

    const int tid = threadIdx.x;
    const int tx = tid & 15, ty = tid >> 4;
    const int m0 = blockIdx.y << 7, n0 = blockIdx.x << 7;

    unsigned long long acc[8][4];
#pragma unroll
    for (int i = 0; i < 8; i++)
#pragma unroll
        for (int j = 0; j < 4; j++) acc[i][j] = 0ULL;

    const int mA = tid >> 2;          // 0..63
    const int kA = (tid & 3) << 2;    // 0,4,8,12
    const int kB = tid >> 5;          // 0..7
    const int nB = (tid & 31) << 2;   // 0..124

    const float* ap = x + (size_t)(m0 + mA) * K_TOT + kA;
    const float* bp = w + (size_t)kB * N_TOT + n0 + nB;

    for (int k0 = 0; k0 < K_TOT; k0 += 16) {
        // load A tile (transposed store)
        float4 a0 = *(const float4*)(ap + k0);
        float4 a1 = *(const float4*)(ap + (size_t)64 * K_TOT + k0);
        As[kA + 0][mA] = a0.x; As[kA + 1][mA] = a0.y;
        As[kA + 2][mA] = a0.z; As[kA + 3][mA] = a0.w;
        As[kA + 0][mA + 64] = a1.x; As[kA + 1][mA + 64] = a1.y;
        As[kA + 2][mA + 64] = a1.z; As[kA + 3][mA + 64] = a1.w;
        // load B tile (natural)
        *(float4*)&Bs[kB][nB]     = *(const float4*)(bp + (size_t)k0 * N_TOT);
        *(float4*)&Bs[kB + 8][nB] = *(const float4*)(bp + (size_t)(k0 + 8) * N_TOT);
        __syncthreads();

#pragma unroll
        for (int k = 0; k < 16; k++) {
            float a[8];
            *(float4*)&a[0] = *(float4*)&As[k][ty << 2];
            *(float4*)&a[4] = *(float4*)&As[k][64 + (ty << 2)];
            unsigned long long b[4];
            {
                ulonglong2 t0 = *(ulonglong2*)&Bs[k][tx << 2];
                ulonglong2 t1 = *(ulonglong2*)&Bs[k][64 + (tx << 2)];
                b[0] = t0.x; b[1] = t0.y; b[2] = t1.x; b[3] = t1.y;
            }
#pragma unroll
            for (int i = 0; i < 8; i++) {
                unsigned long long a2 = dup2(a[i]);
                fma2(acc[i][0], a2, b[0]);
                fma2(acc[i][1], a2, b[1]);
                fma2(acc[i][2], a2, b[2]);
                fma2(acc[i][3], a2, b[3]);
            }
        }
        __syncthreads();
    }

    // epilogue: scatter into [B,H,S,D]-layout Q/K/V
#pragma unroll
    for (int i = 0; i < 8; i++) {
        const int m = m0 + ((i < 4) ? ((ty << 2) + i) : (64 + (ty << 2) + i - 4));
        const int bb = m >> 11;             // /S_LEN
        const int s  = m & (S_LEN - 1);
#pragma unroll
        for (int j = 0; j < 4; j++) {
            float2 v = unpk(acc[i][j]);
            const int nbase = n0 + ((j < 2) ? ((tx << 2) + (j << 1))
                                            : (64 + (tx << 2) + ((j - 2) << 1)));
#pragma unroll
            for (int u = 0; u < 2; u++) {
                const int n = nbase + u;
                const float val = (u == 0) ? v.x : v.y;
                const int which = n >> 10;      // 0=q,1=k,2=v
                const int rem = n & 1023;
                const int h = rem >> 6;
                const int d = rem & 63;
                const size_t dst = (((size_t)(bb * NH + h)) * S_LEN + s) * HD + d;
                if (which == 0)      g_q[dst] = val * 0.125f;   // fold 1/sqrt(D)
                else if (which == 1) g_k[dst] = val;
                else                 g_v[dst] = val;
            }
        }
    }
}

// ============================================================================
// Kernel 2: causal flash attention, fp32, f32x2 packed FMA.
// One CTA = 64 Q rows of one (b,h).  K tile stored transposed [d][c] with a
// 16B-chunk XOR swizzle; the same buffer is reused for P after the S-gemm.
// ============================================================================
__global__ __launch_bounds__(256, 2) void attn_kernel(float* __restrict__ out) {
    __shared__ float Qs[64 * 64];    // [r][d]
    __shared__ float KPs[64 * 64];   // K^T swizzled [d][c], then P [r][c]
    __shared__ float Vs[64 * 64];    // [c][d]

    const int tid = threadIdx.x;
    const int tx = tid & 15, ty = tid >> 4;
    const int qtile = (int)gridDim.x - 1 - (int)blockIdx.x;  // long blocks first
    const int bh = blockIdx.y;
    const int qbase = qtile << 6;
    const float NEG_INF = __int_as_float(0xff800000);

    const float* Qg = g_q + (size_t)bh * S_LEN * HD;
    const float* Kg = g_k + (size_t)bh * S_LEN * HD;
    const float* Vg = g_v + (size_t)bh * S_LEN * HD;

    const int lr = tid >> 2;   // 0..63 (row)
    const int lv = tid & 3;    // 0..3  (vec)

    // load Q tile (already scaled by 1/sqrt(D))
#pragma unroll
    for (int c = 0; c < 4; c++) {
        const int dv = lv + (c << 2);
        *(float4*)&Qs[lr * 64 + (dv << 2)] =
            *(const float4*)(Qg + (size_t)(qbase + lr) * HD + (dv << 2));
    }

    float mrow[4], lrow[4];
    unsigned long long oacc[4][2];
#pragma unroll
    for (int i = 0; i < 4; i++) {
        mrow[i] = NEG_INF; lrow[i] = 0.0f;
        oacc[i][0] = 0ULL; oacc[i][1] = 0ULL;
    }

    for (int kt = 0; kt <= qtile; kt++) {
        const int kbase = kt << 6;
        __syncthreads();  // prior-iter reads done (and Q stores before 1st gemm)

        // load K (transposed + swizzled) and V (natural)
#pragma unroll
        for (int c = 0; c < 4; c++) {
            const int dv = lv + (c << 2);
            const int d0 = dv << 2;
            float4 kv = *(const float4*)(Kg + (size_t)(kbase + lr) * HD + d0);
            const int q = lr >> 2, lo = lr & 3;
            KPs[(d0 + 0) * 64 + ((q ^ ((d0 + 0) & 15)) << 2) + lo] = kv.x;
            KPs[(d0 + 1) * 64 + ((q ^ ((d0 + 1) & 15)) << 2) + lo] = kv.y;
            KPs[(d0 + 2) * 64 + ((q ^ ((d0 + 2) & 15)) << 2) + lo] = kv.z;
            KPs[(d0 + 3) * 64 + ((q ^ ((d0 + 3) & 15)) << 2) + lo] = kv.w;
            *(float4*)&Vs[lr * 64 + d0] =
                *(const float4*)(Vg + (size_t)(kbase + lr) * HD + d0);
        }
        __syncthreads();

        // S = Q K^T : rows r = 4ty+i, cols c = 4tx+j (pairs packed)
        unsigned long long sc2[4][2];
#pragma unroll
        for (int i = 0; i < 4; i++) { sc2[i][0] = 0ULL; sc2[i][1] = 0ULL; }

#pragma unroll
        for (int d0 = 0; d0 < 64; d0 += 4) {
            float4 af[4];
#pragma unroll
            for (int i = 0; i < 4; i++)
                af[i] = *(float4*)&Qs[((ty << 2) + i) * 64 + d0];
            unsigned long long bf[4][2];
#pragma unroll
            for (int dd = 0; dd < 4; dd++) {
                const int d = d0 + dd;
                ulonglong2 t = *(ulonglong2*)&KPs[d * 64 + ((tx ^ (d & 15)) << 2)];
                bf[dd][0] = t.x; bf[dd][1] = t.y;
            }
#pragma unroll
            for (int i = 0; i < 4; i++) {
                unsigned long long a0 = dup2(af[i].x), a1 = dup2(af[i].y);
                unsigned long long a2 = dup2(af[i].z), a3 = dup2(af[i].w);
                fma2(sc2[i][0], a0, bf[0][0]); fma2(sc2[i][1], a0, bf[0][1]);
                fma2(sc2[i][0], a1, bf[1][0]); fma2(sc2[i][1], a1, bf[1][1]);
                fma2(sc2[i][0], a2, bf[2][0]); fma2(sc2[i][1], a2, bf[2][1]);
                fma2(sc2[i][0], a3, bf[3][0]); fma2(sc2[i][1], a3, bf[3][1]);
            }
        }

        // online softmax (row-wise, 16-lane shfl reductions)
        const bool diag = (kt == qtile);
        float pfrag[4][4];
#pragma unroll
        for (int i = 0; i < 4; i++) {
            float2 p01 = unpk(sc2[i][0]);
            float2 p23 = unpk(sc2[i][1]);
            float s0 = p01.x, s1 = p01.y, s2 = p23.x, s3 = p23.y;
            if (diag) {
                const int rg = qbase + (ty << 2) + i;
                const int cg = kbase + (tx << 2);
                if (cg + 0 > rg) s0 = NEG_INF;
                if (cg + 1 > rg) s1 = NEG_INF;
                if (cg + 2 > rg) s2 = NEG_INF;
                if (cg + 3 > rg) s3 = NEG_INF;
            }
            float rmax = fmaxf(fmaxf(s0, s1), fmaxf(s2, s3));
#pragma unroll
            for (int o = 8; o >= 1; o >>= 1)
                rmax = fmaxf(rmax, __shfl_xor_sync(0xffffffffu, rmax, o, 16));
            const float mnew = fmaxf(mrow[i], rmax);
            const float alpha = __expf(mrow[i] - mnew);
            const float p0 = __expf(s0 - mnew);
            const float p1 = __expf(s1 - mnew);
            const float p2 = __expf(s2 - mnew);
            const float p3 = __expf(s3 - mnew);
            float rsum = (p0 + p1) + (p2 + p3);
#pragma unroll
            for (int o = 8; o >= 1; o >>= 1)
                rsum += __shfl_xor_sync(0xffffffffu, rsum, o, 16);
            lrow[i] = lrow[i] * alpha + rsum;
            mrow[i] = mnew;
            unsigned long long al2 = dup2(alpha);
            mul2(oacc[i][0], al2);
            mul2(oacc[i][1], al2);
            pfrag[i][0] = p0; pfrag[i][1] = p1; pfrag[i][2] = p2; pfrag[i][3] = p3;
        }

        __syncthreads();  // everyone done reading KPs as K
#pragma unroll
        for (int i = 0; i < 4; i++)
            *(float4*)&KPs[((ty << 2) + i) * 64 + (tx << 2)] = *(float4*)&pfrag[i][0];
        __syncthreads();  // P visible

        // O += P @ V : rows r = 4ty+i, d-cols 4tx+jj (pairs packed)
#pragma unroll
        for (int c0 = 0; c0 < 64; c0 += 4) {
            float4 pf[4];
#pragma unroll
            for (int i = 0; i < 4; i++)
                pf[i] = *(float4*)&KPs[((ty << 2) + i) * 64 + c0];
            unsigned long long vf[4][2];
#pragma unroll
            for (int k = 0; k < 4; k++) {
                ulonglong2 t = *(ulonglong2*)&Vs[(c0 + k) * 64 + (tx << 2)];
                vf[k][0] = t.x; vf[k][1] = t.y;
            }
#pragma unroll
            for (int i = 0; i < 4; i++) {
                unsigned long long p0 = dup2(pf[i].x), p1 = dup2(pf[i].y);
                unsigned long long p2 = dup2(pf[i].z), p3 = dup2(pf[i].w);
                fma2(oacc[i][0], p0, vf[0][0]); fma2(oacc[i][1], p0, vf[0][1]);
                fma2(oacc[i][0], p1, vf[1][0]); fma2(oacc[i][1], p1, vf[1][1]);
                fma2(oacc[i][0], p2, vf[2][0]); fma2(oacc[i][1], p2, vf[2][1]);
                fma2(oacc[i][0], p3, vf[3][0]); fma2(oacc[i][1], p3, vf[3][1]);
            }
        }
    }

    // write output: out[b, s, h*64 + d]
    const int b = bh >> 4, h = bh & 15;
#pragma unroll
    for (int i = 0; i < 4; i++) {
        const int s = qbase + (ty << 2) + i;
        const float inv = 1.0f / lrow[i];
        float2 o01 = unpk(oacc[i][0]);
        float2 o23 = unpk(oacc[i][1]);
        float4 o4 = make_float4(o01.x * inv, o01.y * inv, o23.x * inv, o23.y * inv);
        *(float4*)(out + ((size_t)b * S_LEN + s) * E_DIM + h * HD + (tx << 2)) = o4;
    }
}

// ============================================================================
// Launch
// ============================================================================
extern "C" void kernel_launch(void* const* d_in, const int* in_sizes, int n_in,
                              void* d_out, int out_size) {
    (void)in_sizes; (void)n_in; (void)out_size;
    const float* x = (const float*)d_in[0];   // [4,2048,1024] fp32
    const float* w = (const float*)d_in[1];   // [1024,3072] fp32
    float* out = (float*)d_out;               // [4,2048,1024] fp32

    qkv_gemm<<<dim3(N_TOT / 128, M_TOT / 128), 256>>>(x, w);
    attn_kernel<<<dim3(S_LEN / 64, B_SZ * NH), 256>>>(out);
}